// round 12
// baseline (speedup 1.0000x reference)
#include <cuda_runtime.h>
#include <cuda_bf16.h>
#include <cstdint>

// ============================================================================
// RBF-SVM head:  out[64,8] = exp(-g*(||x||^2 - 2 x@C^T + ||c||^2)) @ W^T + b
// R12: ncu on fused kernel showed DRAM=43.8%/tensor=16.7%/issue=17.5% ->
// latency-bound, poor load duty cycle. Fix: MT 128->64, smem 32KB/CTA,
// 3 CTAs/SM (440 CTAs, launch_bounds(256,3)) so per-SM CTA phases stagger
// and DRAM demand smooths. Fusion reverted (measured -2us vs 4 kernels).
// ============================================================================

#define GAMMA_F 1e-4f
static constexpr int BATCH  = 64;
static constexpr int NC     = 500;       // real centers
static constexpr int NCP    = 512;       // padded centers
static constexpr int KDIM   = 65536;
static constexpr int NSPLIT = 55;        // K splits (8 tiles * 55 = 440 CTAs ~= 3/SM)
static constexpr int NTILES = 8;         // center tiles of 64
static constexpr int MT     = 64;        // centers per CTA tile
static constexpr int KT     = 64;        // K elements per smem tile
static constexpr int NKT    = KDIM / KT; // 1024 k-tiles total

// ---- device scratch (no allocations allowed) ----
__device__ __nv_bfloat16 g_xb[BATCH * KDIM];       // 8 MB bf16 x
__device__ float g_xsq4[BATCH * 4];                // quarter-row ||x||^2 partials
__device__ float g_csqp[NSPLIT * NCP];             // per-split ||c||^2 partials
__device__ float g_partial[NSPLIT * NCP * BATCH];  // cross partials 7.2 MB
__device__ float g_outp[64 * 64];                  // epi block partials

// ============================================================================
// helpers
// ============================================================================
__device__ __forceinline__ uint32_t smem_u32(const void* p) {
    uint32_t a;
    asm("{ .reg .u64 t; cvta.to.shared.u64 t, %1; cvt.u32.u64 %0, t; }" : "=r"(a) : "l"(p));
    return a;
}

#define SMEM_SWIZZLE_128B(byte_offset) \
    ((byte_offset) ^ (((byte_offset) >> 3) & 0x70))

__device__ __forceinline__ void ldsm_x4(uint32_t* r, uint32_t addr) {
    asm volatile("ldmatrix.sync.aligned.m8n8.x4.shared.b16 {%0,%1,%2,%3}, [%4];"
                 : "=r"(r[0]), "=r"(r[1]), "=r"(r[2]), "=r"(r[3]) : "r"(addr));
}

__device__ __forceinline__ void mma16816(float* d, const uint32_t* a, const uint32_t* b) {
    asm volatile(
        "mma.sync.aligned.m16n8k16.row.col.f32.bf16.bf16.f32 "
        "{%0,%1,%2,%3}, {%4,%5,%6,%7}, {%8,%9}, {%0,%1,%2,%3};\n"
        : "+f"(d[0]), "+f"(d[1]), "+f"(d[2]), "+f"(d[3])
        : "r"(a[0]), "r"(a[1]), "r"(a[2]), "r"(a[3]), "r"(b[0]), "r"(b[1]));
}

__device__ __forceinline__ unsigned pack_bf16x2(float lo, float hi) {
    __nv_bfloat162 t = __floats2bfloat162_rn(lo, hi);
    return *reinterpret_cast<unsigned*>(&t);
}

// ============================================================================
// Kernel 1: x fp32 -> bf16 + quarter-row ||x||^2 partials. grid = 256.
// ============================================================================
__global__ __launch_bounds__(256, 1) void prep_kernel(const float* __restrict__ x) {
    const int b = blockIdx.x >> 2;
    const int q = blockIdx.x & 3;
    const int tid = threadIdx.x;
    const size_t base = (size_t)b * KDIM + (size_t)q * (KDIM / 4);
    const float4* xr = reinterpret_cast<const float4*>(x + base);
    uint2* xo = reinterpret_cast<uint2*>(g_xb + base);
    float sq = 0.f;
    #pragma unroll 4
    for (int i = tid; i < KDIM / 16; i += 256) {
        float4 v = xr[i];
        sq += v.x * v.x + v.y * v.y + v.z * v.z + v.w * v.w;
        uint2 o;
        o.x = pack_bf16x2(v.x, v.y);
        o.y = pack_bf16x2(v.z, v.w);
        xo[i] = o;
    }
    for (int off = 16; off > 0; off >>= 1) sq += __shfl_down_sync(0xffffffffu, sq, off);
    __shared__ float sm[8];
    if ((tid & 31) == 0) sm[tid >> 5] = sq;
    __syncthreads();
    if (tid == 0) {
        float t = 0.f;
        #pragma unroll
        for (int k = 0; k < 8; k++) t += sm[k];
        g_xsq4[b * 4 + q] = t;
    }
}

// ============================================================================
// Kernel 2: split-K bf16 HMMA GEMM. grid = 8 tiles * 55 splits = 440 CTAs.
//   smA = centers tile [64 x 64] bf16 SW128 (8 KB x2)
//   smB = x tile       [64 x 64] bf16 SW128 via cp.async (8 KB x2)
//   warp (m = wid&3, nh = wid>>2): acc 16 centers x 32 batch (16 fp32 regs)
// ============================================================================
__global__ __launch_bounds__(256, 3) void mma_kernel(const float* __restrict__ centers) {
    __shared__ __align__(1024) unsigned char smA[2][MT * 128];      // 2 x 8 KB
    __shared__ __align__(1024) unsigned char smB[2][BATCH * 128];   // 2 x 8 KB

    const int tid  = threadIdx.x;
    const int wid  = tid >> 5;
    const int lane = tid & 31;
    const int tile  = blockIdx.x & 7;
    const int split = blockIdx.x >> 3;
    const int t0 = split * NKT / NSPLIT;
    const int t1 = (split + 1) * NKT / NSPLIT;

    const uint32_t smA_u = smem_u32(smA);
    const uint32_t smB_u = smem_u32(smB);

    // ---- A load mapping: row = tid>>2 (64 rows), quarter q = tid&3 ----
    const int row_c = tid >> 2;
    const int q_c   = tid & 3;

    auto load_c = [&](int kt, float4* cr) {
        const size_t kb = (size_t)kt * KT + q_c * 16;
        const int g = tile * MT + row_c;
        if (g < NC) {
            const float4* src = reinterpret_cast<const float4*>(centers + (size_t)g * KDIM + kb);
            #pragma unroll
            for (int j = 0; j < 4; j++) cr[j] = src[j];
        } else {
            #pragma unroll
            for (int j = 0; j < 4; j++) cr[j] = make_float4(0.f, 0.f, 0.f, 0.f);
        }
    };
    auto cpasync_b = [&](int kt, int buf) {
        #pragma unroll
        for (int j = 0; j < 2; j++) {
            const int c = tid * 2 + j;           // 512 chunks of 16B
            const int row = c >> 3, col = c & 7;
            const __nv_bfloat16* src = g_xb + (size_t)row * KDIM + (size_t)kt * KT + col * 8;
            const uint32_t off = (uint32_t)(row * 128 + col * 16);
            const uint32_t dst = smB_u + buf * 8192 + SMEM_SWIZZLE_128B(off);
            asm volatile("cp.async.ca.shared.global [%0], [%1], 16;" :: "r"(dst), "l"(src));
        }
        asm volatile("cp.async.commit_group;" ::: "memory");
    };

    float csq = 0.f;
    auto store_a = [&](int buf, const float4* cr) {
        #pragma unroll
        for (int j = 0; j < 4; j++) {
            const float4 v = cr[j];
            csq += v.x * v.x + v.y * v.y + v.z * v.z + v.w * v.w;
            uint2 o;
            o.x = pack_bf16x2(v.x, v.y);
            o.y = pack_bf16x2(v.z, v.w);
            const uint32_t off = SMEM_SWIZZLE_128B((uint32_t)(row_c * 128 + q_c * 32 + j * 8));
            *reinterpret_cast<uint2*>(&smA[buf][0] + off) = o;
        }
    };

    // ---- ldmatrix lane addressing (SW128) ----
    const int m_w  = wid & 3;     // 16-row block within the 64 centers
    const int nh_w = wid >> 2;    // batch half (32 cols)
    const uint32_t a_row = (uint32_t)((m_w * 16 + (lane & 15)) * 128 + ((lane >> 4) * 16));
    const uint32_t a_swz = SMEM_SWIZZLE_128B(a_row);
    const uint32_t b_rk  = (uint32_t)((lane & 7) + ((lane >> 4) & 1) * 8);
    const uint32_t b_k16 = (uint32_t)(((lane >> 3) & 1) * 16);
    uint32_t b_off[2];
    #pragma unroll
    for (int p = 0; p < 2; p++) {
        const uint32_t o = (nh_w * 32 + p * 16 + b_rk) * 128 + b_k16;
        b_off[p] = SMEM_SWIZZLE_128B(o);
    }

    float acc[16];
    #pragma unroll
    for (int i = 0; i < 16; i++) acc[i] = 0.f;

    // ---- prologue ----
    float4 creg[4];
    cpasync_b(t0, 0);
    load_c(t0, creg);
    store_a(0, creg);
    if (t0 + 1 < t1) load_c(t0 + 1, creg);

    for (int it = t0; it < t1; ++it) {
        const int buf = (it - t0) & 1;
        const bool has1 = (it + 1 < t1);
        const bool has2 = (it + 2 < t1);

        if (has1) cpasync_b(it + 1, buf ^ 1);
        if (has1) store_a(buf ^ 1, creg);

        asm volatile("cp.async.wait_group %0;" :: "n"(0) : "memory");
        __syncthreads();   // buf data (stored last iter / prologue) + cp.async visible

        if (has2) load_c(it + 2, creg);   // LDGs in flight during compute

        // ---- compute tile it: 4 k-steps ----
        const uint32_t abase = smA_u + (uint32_t)buf * 8192u + a_swz;
        const uint32_t bbase = smB_u + (uint32_t)buf * 8192u;
        #pragma unroll
        for (int ks = 0; ks < 4; ks++) {
            uint32_t a[4];
            ldsm_x4(a, abase ^ (uint32_t)(ks * 32));
            #pragma unroll
            for (int p = 0; p < 2; p++) {
                uint32_t b[4];
                ldsm_x4(b, (bbase + b_off[p]) ^ (uint32_t)(ks * 32));
                mma16816(&acc[(p * 2 + 0) * 4], a, &b[0]);
                mma16816(&acc[(p * 2 + 1) * 4], a, &b[2]);
            }
        }
        __syncthreads();   // smem[buf] consumed; safe to overwrite next iter
    }

    // ---- write ||c||^2 split partials (reduce 4 threads per row) ----
    {
        float v = csq;
        v += __shfl_down_sync(0xffffffffu, v, 2, 4);
        v += __shfl_down_sync(0xffffffffu, v, 1, 4);
        if (q_c == 0)
            g_csqp[split * NCP + tile * MT + row_c] = v;
    }

    // ---- write cross partials ----
    {
        const int g = lane >> 2;
        const int t2 = (lane & 3) * 2;
        #pragma unroll
        for (int nblk = 0; nblk < 4; nblk++) {
            const float* d = &acc[nblk * 4];
            const int n0 = tile * MT + m_w * 16 + g;
            const int b0 = nh_w * 32 + nblk * 8 + t2;
            *reinterpret_cast<float2*>(g_partial + ((size_t)split * NCP + n0) * BATCH + b0)
                = make_float2(d[0], d[1]);
            *reinterpret_cast<float2*>(g_partial + ((size_t)split * NCP + n0 + 8) * BATCH + b0)
                = make_float2(d[2], d[3]);
        }
    }
}

// ============================================================================
// Kernel 3: reduce splits + rbf + partial FC. grid = 64 blocks.
// ============================================================================
__global__ __launch_bounds__(256, 1) void epi_kernel(const float* __restrict__ fc_w) {
    __shared__ float s_w[8 * 64];      // [h][nl]
    __shared__ float s_csq[64];
    __shared__ float s_xsq[8];
    __shared__ float s_rbf[64 * 8];    // [nl][b8]
    const int tid = threadIdx.x;
    const int nb = (blockIdx.x & 7) * 64;
    const int bc = blockIdx.x >> 3;

    if (tid < 64) {
        float c = 0.f;
        for (int s = 0; s < NSPLIT; s++) c += g_csqp[s * NCP + nb + tid];
        s_csq[tid] = c;
    }
    if (tid >= 64 && tid < 72) {
        const int b = bc * 8 + (tid - 64);
        s_xsq[tid - 64] = g_xsq4[b * 4] + g_xsq4[b * 4 + 1] + g_xsq4[b * 4 + 2] + g_xsq4[b * 4 + 3];
    }
    for (int i = tid; i < 512; i += 256) {
        const int h = i >> 6, nl = i & 63, n = nb + nl;
        s_w[i] = (n < NC) ? fc_w[h * NC + n] : 0.f;
    }
    __syncthreads();

    #pragma unroll
    for (int p = tid; p < 512; p += 256) {
        const int nl = p >> 3, b8 = p & 7;
        float cr = 0.f;
        for (int s = 0; s < NSPLIT; s++)
            cr += g_partial[((size_t)s * NCP + nb + nl) * BATCH + bc * 8 + b8];
        const float dist = s_xsq[b8] - 2.f * cr + s_csq[nl];
        s_rbf[p] = __expf(-GAMMA_F * dist);
    }
    __syncthreads();

    if (tid < 64) {
        const int b8 = tid >> 3, h = tid & 7;
        float accv = 0.f;
        #pragma unroll
        for (int nl = 0; nl < 64; nl++) accv += s_rbf[nl * 8 + b8] * s_w[h * 64 + nl];
        g_outp[blockIdx.x * 64 + tid] = accv;
    }
}

// ============================================================================
// Kernel 4: sum 8 center-block partials + fc_b -> out[64,8]
// ============================================================================
__global__ void final_kernel(const float* __restrict__ fc_b, float* __restrict__ out) {
    const int o = threadIdx.x;          // 512: b = o>>3, h = o&7
    const int b = o >> 3, h = o & 7;
    const int bc = b >> 3, b8 = b & 7;
    float a = fc_b[h];
    #pragma unroll
    for (int nbk = 0; nbk < 8; nbk++)
        a += g_outp[(bc * 8 + nbk) * 64 + b8 * 8 + h];
    out[o] = a;
}

// ============================================================================
extern "C" void kernel_launch(void* const* d_in, const int* in_sizes, int n_in,
                              void* d_out, int out_size) {
    (void)in_sizes; (void)n_in; (void)out_size;
    const float* x       = (const float*)d_in[0];
    const float* centers = (const float*)d_in[1];
    const float* fc_w    = (const float*)d_in[2];
    const float* fc_b    = (const float*)d_in[3];
    float* out = (float*)d_out;

    prep_kernel<<<BATCH * 4, 256>>>(x);
    mma_kernel<<<NTILES * NSPLIT, 256>>>(centers);
    epi_kernel<<<64, 256>>>(fc_w);
    final_kernel<<<1, 512>>>(fc_b, out);
}